// round 15
// baseline (speedup 1.0000x reference)
#include <cuda_runtime.h>
#include <cuda_bf16.h>
#include <cuda_fp16.h>
#include <cstdint>
#include <cstddef>

// ---------------- problem constants ----------------
#define BTOK 4096
#define HDIM 4096
#define VDIM 32000
#define SEQT 512
#define IGNORE_IDX (-100)

// ---------------- FP8 GEMM tiling (champion config: 2 CTAs/SM) ----------------
#define BM 128
#define BN 128
#define BKB 128                  // K bytes per chunk
#define NK (HDIM / BKB)          // 32 chunks
#define NSTAGE 3
#define ROWB 128
#define A_BYTES (BM * ROWB)      // 16384
#define STAGE_BYTES (A_BYTES + BN * ROWB)   // 32768
#define RED_OFF (NSTAGE * STAGE_BYTES)      // 98304
#define SMEM_GEMM (RED_OFF + 2048)
#define NTIL (VDIM / BN)         // 250
#define SCALE 64.0f
#define INVS (1.0f / 4096.0f)

#define SWZ(o) ((o) ^ (((o) >> 3) & 0x70))

// ---------------- device scratch ----------------
__device__ __align__(256) uint8_t g_xq[2][(size_t)BTOK * HDIM];
__device__ __align__(256) uint8_t g_wq[2][(size_t)VDIM * HDIM];
__device__ float g_plse[2][BTOK][NTIL];
__device__ float g_tgt[2][BTOK];
__device__ float g_logp[2][BTOK];
__device__ int   g_tidx[BTOK];

// ---------------- helpers ----------------
__device__ __forceinline__ uint32_t smem_u32(const void* p) {
    return (uint32_t)__cvta_generic_to_shared(p);
}
__device__ __forceinline__ void ldmx4(uint32_t* r, uint32_t addr) {
    asm volatile("ldmatrix.sync.aligned.m8n8.x4.shared.b16 {%0,%1,%2,%3}, [%4];\n"
                 : "=r"(r[0]), "=r"(r[1]), "=r"(r[2]), "=r"(r[3]) : "r"(addr));
}
// fp8 x fp8 -> fp16 accumulators (best measured path on sm_103 legacy pipe)
__device__ __forceinline__ void mma_fp8_h(uint32_t* d, const uint32_t* a,
                                          uint32_t b0, uint32_t b1) {
    asm volatile("mma.sync.aligned.m16n8k32.row.col.f16.e4m3.e4m3.f16 "
                 "{%0,%1}, {%2,%3,%4,%5}, {%6,%7}, {%0,%1};\n"
                 : "+r"(d[0]), "+r"(d[1])
                 : "r"(a[0]), "r"(a[1]), "r"(a[2]), "r"(a[3]), "r"(b0), "r"(b1));
}
#define CPA16(dst, src) asm volatile("cp.async.cg.shared.global [%0], [%1], 16;" :: "r"(dst), "l"(src))
#define CP_COMMIT()     asm volatile("cp.async.commit_group;")
#define CP_WAIT1()      asm volatile("cp.async.wait_group 1;")
#define CP_WAIT0()      asm volatile("cp.async.wait_group 0;")

__device__ __forceinline__ uint32_t pack4_e4m3(float f0, float f1, float f2, float f3) {
    uint16_t lo, hi;
    asm("cvt.rn.satfinite.e4m3x2.f32 %0, %1, %2;" : "=h"(lo) : "f"(f1), "f"(f0));
    asm("cvt.rn.satfinite.e4m3x2.f32 %0, %1, %2;" : "=h"(hi) : "f"(f3), "f"(f2));
    return (uint32_t)lo | ((uint32_t)hi << 16);
}

// ---------------- kernel 0: normalize targets ----------------
__global__ void norm_targets_kernel(const void* traw) {
    __shared__ int notI64;
    const int* t32 = (const int*)traw;
    if (threadIdx.x == 0) notI64 = 0;
    __syncthreads();
    for (int i = threadIdx.x; i < BTOK / 2; i += blockDim.x) {
        int hi = t32[2 * i + 1];
        if (hi != 0 && hi != -1) notI64 = 1;
    }
    __syncthreads();
    if (notI64) {
        for (int i = threadIdx.x; i < BTOK; i += blockDim.x) g_tidx[i] = t32[i];
    } else {
        const long long* t64 = (const long long*)traw;
        for (int i = threadIdx.x; i < BTOK; i += blockDim.x) g_tidx[i] = (int)t64[i];
    }
}

// ---------------- kernel 1a: activations fp32 -> scaled e4m3 (2 granules/thread) --
__global__ void convert_x_kernel(const float4* __restrict__ x0, const float4* __restrict__ x1) {
    const size_t n4 = (size_t)BTOK * HDIM / 4;
    const int model = blockIdx.y;
    const float4* __restrict__ src = model ? x1 : x0;
    uint32_t* __restrict__ dst = reinterpret_cast<uint32_t*>(g_xq[model]);
    size_t i = (size_t)blockIdx.x * blockDim.x + threadIdx.x;
    const size_t stride = (size_t)gridDim.x * blockDim.x;
#pragma unroll
    for (int r = 0; r < 2; r++) {
        if (i < n4) {
            float4 v = src[i];
            dst[i] = pack4_e4m3(v.x * SCALE, v.y * SCALE, v.z * SCALE, v.w * SCALE);
        }
        i += stride;
    }
}
// ---------------- kernel 1b: weights (2 granules/thread, both models) ------------
__global__ void convert_w_kernel(const float4* __restrict__ w0, const float4* __restrict__ w1) {
    const size_t n4 = (size_t)VDIM * HDIM / 4;
    const int model = blockIdx.y;
    const float4* __restrict__ src = model ? w1 : w0;
    uint32_t* __restrict__ dst = reinterpret_cast<uint32_t*>(g_wq[model]);
    size_t i = (size_t)blockIdx.x * blockDim.x + threadIdx.x;
    const size_t stride = (size_t)gridDim.x * blockDim.x;
#pragma unroll
    for (int r = 0; r < 2; r++) {
        if (i < n4) {
            float4 v = src[i];
            dst[i] = pack4_e4m3(v.x * SCALE, v.y * SCALE, v.z * SCALE, v.w * SCALE);
        }
        i += stride;
    }
}

// ---------------- kernel 2: FP8 GEMM, fp16 accum, 2 CTAs/SM, fused LSE ------------
// 8 warps, warp tile 32x64. 3-stage cp.async ring, 1 __syncthreads per chunk.
// Prefetch cp.asyncs spread across the 4 kk MMA groups (kills post-barrier LSU convoy).
__global__ void __launch_bounds__(256, 2)
gemm_lse_kernel(const float* __restrict__ bias0, const float* __restrict__ bias1) {
    extern __shared__ char smem[];
    const uint32_t sb = smem_u32(smem);
    const int mtile = blockIdx.x, ntile = blockIdx.y, model = blockIdx.z;
    const uint8_t* __restrict__ Ab = g_xq[model] + (size_t)(mtile * BM) * HDIM;
    const uint8_t* __restrict__ Bb = g_wq[model] + (size_t)(ntile * BN) * HDIM;
    const float* __restrict__ bias = model ? bias1 : bias0;

    const int tid = threadIdx.x;
    const int lane = tid & 31, warp = tid >> 5;
    const int wm = warp & 3, wn = warp >> 2;   // 4x2 warps, warp tile 32x64

    uint32_t acc[2][8][2];                     // f16x2 accumulators
#pragma unroll
    for (int i = 0; i < 2; i++)
#pragma unroll
        for (int j = 0; j < 8; j++) { acc[i][j][0] = 0u; acc[i][j][1] = 0u; }

    // one 16B granule of the chunk: task index i in [0,8)
    auto issue_one = [&](int s, int kt, int i) {
        const uint32_t stA = sb + s * STAGE_BYTES;
        const int k0 = kt * BKB;
        int task = i * 256 + tid;
        if (task < 1024) {
            int row = task >> 3, ch = task & 7;
            uint32_t rel = (uint32_t)(row * ROWB + ch * 16);
            CPA16(stA + SWZ(rel), Ab + (size_t)row * HDIM + k0 + ch * 16);
        } else {
            int t2 = task - 1024;
            int row = t2 >> 3, ch = t2 & 7;
            uint32_t rel = (uint32_t)(row * ROWB + ch * 16);
            CPA16(stA + A_BYTES + SWZ(rel), Bb + (size_t)row * HDIM + k0 + ch * 16);
        }
    };
    auto issue_all = [&](int s, int kt) {
#pragma unroll
        for (int i = 0; i < 8; i++) issue_one(s, kt, i);
    };

    const uint32_t lr = (uint32_t)(lane & 15);
    const uint32_t lc16 = (uint32_t)(lane >> 4) * 16;

    // fragment loader for one kk sub-step
    auto load_frags = [&](uint32_t aB, uint32_t bB, int kk,
                          uint32_t af[2][4], uint32_t bfr[4][4]) {
        const uint32_t cb = (uint32_t)kk * 32 + lc16;
#pragma unroll
        for (int mi = 0; mi < 2; mi++) {
            uint32_t rel = (uint32_t)(wm * 32 + mi * 16 + lr) * ROWB + cb;
            ldmx4(af[mi], aB + SWZ(rel));
        }
#pragma unroll
        for (int nb = 0; nb < 4; nb++) {
            uint32_t rel = (uint32_t)(wn * 64 + nb * 16 + lr) * ROWB + cb;
            ldmx4(bfr[nb], bB + SWZ(rel));
        }
    };

    issue_all(0, 0); CP_COMMIT();
    issue_all(1, 1); CP_COMMIT();

    int st = 0;
    for (int kt = 0; kt < NK; kt++) {
        if (kt == NK - 1) { CP_WAIT0(); } else { CP_WAIT1(); }
        __syncthreads();
        const bool pre = (kt + 2 < NK);
        int ps = st + 2; if (ps >= NSTAGE) ps -= NSTAGE;

        const uint32_t aB = sb + st * STAGE_BYTES;
        const uint32_t bB = aB + A_BYTES;

        uint32_t af[2][2][4], bfr[2][4][4];
        load_frags(aB, bB, 0, af[0], bfr[0]);
#pragma unroll
        for (int kk = 0; kk < 4; kk++) {
            const int cur = kk & 1;
            if (kk < 3) load_frags(aB, bB, kk + 1, af[cur ^ 1], bfr[cur ^ 1]);
#pragma unroll
            for (int mi = 0; mi < 2; mi++)
#pragma unroll
                for (int nj = 0; nj < 8; nj++)
                    mma_fp8_h(acc[mi][nj], af[cur][mi],
                              bfr[cur][nj >> 1][nj & 1], bfr[cur][nj >> 1][2 + (nj & 1)]);
            // trickle 2 of the 8 prefetch cp.asyncs after each MMA group
            if (pre) {
                issue_one(ps, kt + 2, 2 * kk);
                issue_one(ps, kt + 2, 2 * kk + 1);
            }
        }
        if (pre) CP_COMMIT();
        if (++st == NSTAGE) st = 0;
    }

    // ------- epilogue: f16->f32, scale, + bias, per-row LSE over 128 cols ----------
    const int qr = lane >> 2, qc = lane & 3;
    float bb[16];
#pragma unroll
    for (int nj = 0; nj < 8; nj++) {
        int col = ntile * BN + wn * 64 + nj * 8 + qc * 2;
        bb[2 * nj]     = __ldg(bias + col);
        bb[2 * nj + 1] = __ldg(bias + col + 1);
    }
    float v[2][8][4];
#pragma unroll
    for (int mi = 0; mi < 2; mi++)
#pragma unroll
        for (int nj = 0; nj < 8; nj++) {
#pragma unroll
            for (int h = 0; h < 2; h++) {
                __half2 hv = *reinterpret_cast<__half2*>(&acc[mi][nj][h]);
                float2 f = __half22float2(hv);
                v[mi][nj][2 * h]     = f.x * INVS + bb[2 * nj];
                v[mi][nj][2 * h + 1] = f.y * INVS + bb[2 * nj + 1];
            }
        }

    float* sMax = (float*)(smem + RED_OFF);          // [128][2]
    float* sSum = (float*)(smem + RED_OFF + 1024);   // [128][2]
#pragma unroll
    for (int mi = 0; mi < 2; mi++) {
#pragma unroll
        for (int h = 0; h < 2; h++) {
            float m = -3.0e38f;
#pragma unroll
            for (int nj = 0; nj < 8; nj++)
                m = fmaxf(m, fmaxf(v[mi][nj][2 * h], v[mi][nj][2 * h + 1]));
            m = fmaxf(m, __shfl_xor_sync(0xffffffffu, m, 1));
            m = fmaxf(m, __shfl_xor_sync(0xffffffffu, m, 2));
            float s = 0.f;
#pragma unroll
            for (int nj = 0; nj < 8; nj++) {
                s += __expf(v[mi][nj][2 * h] - m);
                s += __expf(v[mi][nj][2 * h + 1] - m);
            }
            s += __shfl_xor_sync(0xffffffffu, s, 1);
            s += __shfl_xor_sync(0xffffffffu, s, 2);
            if (qc == 0) {
                int r = wm * 32 + mi * 16 + h * 8 + qr;
                sMax[r * 2 + wn] = m;
                sSum[r * 2 + wn] = s;
            }
        }
    }
    __syncthreads();
    if (tid < BM) {
        float ma = sMax[tid * 2], mb = sMax[tid * 2 + 1];
        float mm = fmaxf(ma, mb);
        float ss = sSum[tid * 2] * __expf(ma - mm) + sSum[tid * 2 + 1] * __expf(mb - mm);
        g_plse[model][mtile * BM + tid][ntile] = mm + logf(ss);
    }
}

// ---------------- kernel 3: exact fp32 target logits ----------------
__global__ void tgt_kernel(const float* __restrict__ x0, const float* __restrict__ w0,
                           const float* __restrict__ b0, const float* __restrict__ x1,
                           const float* __restrict__ w1, const float* __restrict__ b1) {
    int gw = (int)((blockIdx.x * blockDim.x + threadIdx.x) >> 5);
    int lane = threadIdx.x & 31;
    if (gw >= 2 * BTOK) return;
    int model = gw >> 12, t = gw & (BTOK - 1);
    int tg = g_tidx[t];
    float r = 0.f;
    if (tg >= 0 && tg < VDIM) {
        const float4* x4 = (const float4*)((model ? x1 : x0) + (size_t)t * HDIM);
        const float4* w4 = (const float4*)((model ? w1 : w0) + (size_t)tg * HDIM);
        float s = 0.f;
        for (int k = lane; k < HDIM / 4; k += 32) {
            float4 a = x4[k], bbk = w4[k];
            s = fmaf(a.x, bbk.x, fmaf(a.y, bbk.y, fmaf(a.z, bbk.z, fmaf(a.w, bbk.w, s))));
        }
#pragma unroll
        for (int o = 16; o; o >>= 1) s += __shfl_xor_sync(0xffffffffu, s, o);
        r = s + (model ? b1 : b0)[tg];
    }
    if (lane == 0) g_tgt[model][t] = r;
}

// ---------------- kernel 4: merge partial LSEs ----------------
__global__ void lse_kernel() {
    int gw = (int)((blockIdx.x * blockDim.x + threadIdx.x) >> 5);
    int lane = threadIdx.x & 31;
    if (gw >= 2 * BTOK) return;
    int model = gw >> 12, t = gw & (BTOK - 1);
    float m = -3.0e38f;
    for (int i = lane; i < NTIL; i += 32) m = fmaxf(m, g_plse[model][t][i]);
#pragma unroll
    for (int o = 16; o; o >>= 1) m = fmaxf(m, __shfl_xor_sync(0xffffffffu, m, o));
    float s = 0.f;
    for (int i = lane; i < NTIL; i += 32) s += expf(g_plse[model][t][i] - m);
#pragma unroll
    for (int o = 16; o; o >>= 1) s += __shfl_xor_sync(0xffffffffu, s, o);
    if (lane == 0) {
        int tg = g_tidx[t];
        g_logp[model][t] = (tg == IGNORE_IDX) ? 0.f : (g_tgt[model][t] - (m + logf(s)));
    }
}

// ---------------- kernel 5: sequence sums + DPO loss ----------------
__global__ void loss_kernel(float* __restrict__ out) {
    __shared__ double seq[16];
    int tid = threadIdx.x;
    if (tid < 16) {
        int model = tid >> 3, s = tid & 7;
        double a = 0.0;
        for (int t = 0; t < SEQT; t++) a += (double)g_logp[model][s * SEQT + t];
        seq[tid] = a;
    }
    __syncthreads();
    if (tid == 0) {
        double L = 0.0;
        for (int p = 0; p < 4; p++) {
            double c = seq[p], r = seq[4 + p];
            double rc = seq[8 + p], rr = seq[12 + p];
            double d = 0.1 * ((c - rc) - (r - rr));
            double nl = (d > 0.0) ? log1p(exp(-d)) : (-d + log1p(exp(d)));
            L += nl;
        }
        out[0] = (float)(L / 4.0);
    }
}

// ---------------- launch ----------------
extern "C" void kernel_launch(void* const* d_in, const int* in_sizes, int n_in,
                              void* d_out, int out_size) {
    const float* x  = (const float*)d_in[0];
    const float* w  = (const float*)d_in[1];
    const float* b  = (const float*)d_in[2];
    const float* rx = (const float*)d_in[3];
    const float* rw = (const float*)d_in[4];
    const float* rb = (const float*)d_in[5];
    const void*  tg = d_in[6];

    norm_targets_kernel<<<1, 256>>>(tg);

    unsigned gx  = (unsigned)(((size_t)BTOK * HDIM / 4 + 511) / 512);
    unsigned gwv = (unsigned)(((size_t)VDIM * HDIM / 4 + 511) / 512);
    convert_x_kernel<<<dim3(gx, 2), 256>>>((const float4*)x, (const float4*)rx);
    convert_w_kernel<<<dim3(gwv, 2), 256>>>((const float4*)w, (const float4*)rw);

    cudaFuncSetAttribute(gemm_lse_kernel,
                         cudaFuncAttributeMaxDynamicSharedMemorySize, SMEM_GEMM);
    dim3 gg(BTOK / BM, VDIM / BN, 2);   // (32, 250, 2), mtile fastest
    gemm_lse_kernel<<<gg, 256, SMEM_GEMM>>>(b, rb);

    tgt_kernel<<<(2 * BTOK) / 8, 256>>>(x, w, b, rx, rw, rb);
    lse_kernel<<<(2 * BTOK) / 8, 256>>>();
    loss_kernel<<<1, 256>>>((float*)d_out);
}

// round 16
// speedup vs baseline: 1.0387x; 1.0387x over previous
#include <cuda_runtime.h>
#include <cuda_bf16.h>
#include <cuda_fp16.h>
#include <cstdint>
#include <cstddef>

// ---------------- problem constants ----------------
#define BTOK 4096
#define HDIM 4096
#define VDIM 32000
#define SEQT 512
#define IGNORE_IDX (-100)

// ---------------- FP8 GEMM tiling (champion config: 2 CTAs/SM, measured 5138us) ---
#define BM 128
#define BN 128
#define BKB 128                  // K bytes per chunk
#define NK (HDIM / BKB)          // 32 chunks
#define NSTAGE 3
#define ROWB 128
#define A_BYTES (BM * ROWB)      // 16384
#define STAGE_BYTES (A_BYTES + BN * ROWB)   // 32768
#define RED_OFF (NSTAGE * STAGE_BYTES)      // 98304
#define SMEM_GEMM (RED_OFF + 2048)
#define NTIL (VDIM / BN)         // 250
#define SCALE 64.0f
#define INVS (1.0f / 4096.0f)

#define SWZ(o) ((o) ^ (((o) >> 3) & 0x70))

// ---------------- device scratch ----------------
__device__ __align__(256) uint8_t g_xq[2][(size_t)BTOK * HDIM];
__device__ __align__(256) uint8_t g_wq[2][(size_t)VDIM * HDIM];
__device__ float g_plse[2][BTOK][NTIL];
__device__ float g_tgt[2][BTOK];
__device__ float g_logp[2][BTOK];
__device__ int   g_tidx[BTOK];

// ---------------- helpers ----------------
__device__ __forceinline__ uint32_t smem_u32(const void* p) {
    return (uint32_t)__cvta_generic_to_shared(p);
}
__device__ __forceinline__ void ldmx4(uint32_t* r, uint32_t addr) {
    asm volatile("ldmatrix.sync.aligned.m8n8.x4.shared.b16 {%0,%1,%2,%3}, [%4];\n"
                 : "=r"(r[0]), "=r"(r[1]), "=r"(r[2]), "=r"(r[3]) : "r"(addr));
}
// fp8 x fp8 -> fp16 accumulators (best measured path on sm_103 legacy pipe)
__device__ __forceinline__ void mma_fp8_h(uint32_t* d, const uint32_t* a,
                                          uint32_t b0, uint32_t b1) {
    asm volatile("mma.sync.aligned.m16n8k32.row.col.f16.e4m3.e4m3.f16 "
                 "{%0,%1}, {%2,%3,%4,%5}, {%6,%7}, {%0,%1};\n"
                 : "+r"(d[0]), "+r"(d[1])
                 : "r"(a[0]), "r"(a[1]), "r"(a[2]), "r"(a[3]), "r"(b0), "r"(b1));
}
#define CPA16(dst, src) asm volatile("cp.async.cg.shared.global [%0], [%1], 16;" :: "r"(dst), "l"(src))
#define CP_COMMIT()     asm volatile("cp.async.commit_group;")
#define CP_WAIT1()      asm volatile("cp.async.wait_group 1;")
#define CP_WAIT0()      asm volatile("cp.async.wait_group 0;")

__device__ __forceinline__ uint32_t pack4_e4m3(float f0, float f1, float f2, float f3) {
    uint16_t lo, hi;
    asm("cvt.rn.satfinite.e4m3x2.f32 %0, %1, %2;" : "=h"(lo) : "f"(f1), "f"(f0));
    asm("cvt.rn.satfinite.e4m3x2.f32 %0, %1, %2;" : "=h"(hi) : "f"(f3), "f"(f2));
    return (uint32_t)lo | ((uint32_t)hi << 16);
}

// ---------------- kernel 0: normalize targets ----------------
__global__ void norm_targets_kernel(const void* traw) {
    __shared__ int notI64;
    const int* t32 = (const int*)traw;
    if (threadIdx.x == 0) notI64 = 0;
    __syncthreads();
    for (int i = threadIdx.x; i < BTOK / 2; i += blockDim.x) {
        int hi = t32[2 * i + 1];
        if (hi != 0 && hi != -1) notI64 = 1;
    }
    __syncthreads();
    if (notI64) {
        for (int i = threadIdx.x; i < BTOK; i += blockDim.x) g_tidx[i] = t32[i];
    } else {
        const long long* t64 = (const long long*)traw;
        for (int i = threadIdx.x; i < BTOK; i += blockDim.x) g_tidx[i] = (int)t64[i];
    }
}

// ---------------- kernel 1a: activations fp32 -> scaled e4m3 (2 granules/thread) --
__global__ void convert_x_kernel(const float4* __restrict__ x0, const float4* __restrict__ x1) {
    const size_t n4 = (size_t)BTOK * HDIM / 4;
    const int model = blockIdx.y;
    const float4* __restrict__ src = model ? x1 : x0;
    uint32_t* __restrict__ dst = reinterpret_cast<uint32_t*>(g_xq[model]);
    size_t i = (size_t)blockIdx.x * blockDim.x + threadIdx.x;
    const size_t stride = (size_t)gridDim.x * blockDim.x;
#pragma unroll
    for (int r = 0; r < 2; r++) {
        if (i < n4) {
            float4 v = src[i];
            dst[i] = pack4_e4m3(v.x * SCALE, v.y * SCALE, v.z * SCALE, v.w * SCALE);
        }
        i += stride;
    }
}
// ---------------- kernel 1b: weights (2 granules/thread, both models) ------------
__global__ void convert_w_kernel(const float4* __restrict__ w0, const float4* __restrict__ w1) {
    const size_t n4 = (size_t)VDIM * HDIM / 4;
    const int model = blockIdx.y;
    const float4* __restrict__ src = model ? w1 : w0;
    uint32_t* __restrict__ dst = reinterpret_cast<uint32_t*>(g_wq[model]);
    size_t i = (size_t)blockIdx.x * blockDim.x + threadIdx.x;
    const size_t stride = (size_t)gridDim.x * blockDim.x;
#pragma unroll
    for (int r = 0; r < 2; r++) {
        if (i < n4) {
            float4 v = src[i];
            dst[i] = pack4_e4m3(v.x * SCALE, v.y * SCALE, v.z * SCALE, v.w * SCALE);
        }
        i += stride;
    }
}

// ---------------- kernel 2: FP8 GEMM, fp16 accum, 2 CTAs/SM, fused LSE ------------
// 8 warps, warp tile 32x64. 3-stage cp.async ring, 1 __syncthreads per chunk.
// kk-level fragment double-buffering (champion, measured 5138 us).
__global__ void __launch_bounds__(256, 2)
gemm_lse_kernel(const float* __restrict__ bias0, const float* __restrict__ bias1) {
    extern __shared__ char smem[];
    const uint32_t sb = smem_u32(smem);
    const int mtile = blockIdx.x, ntile = blockIdx.y, model = blockIdx.z;
    const uint8_t* __restrict__ Ab = g_xq[model] + (size_t)(mtile * BM) * HDIM;
    const uint8_t* __restrict__ Bb = g_wq[model] + (size_t)(ntile * BN) * HDIM;
    const float* __restrict__ bias = model ? bias1 : bias0;

    const int tid = threadIdx.x;
    const int lane = tid & 31, warp = tid >> 5;
    const int wm = warp & 3, wn = warp >> 2;   // 4x2 warps, warp tile 32x64

    uint32_t acc[2][8][2];                     // f16x2 accumulators
#pragma unroll
    for (int i = 0; i < 2; i++)
#pragma unroll
        for (int j = 0; j < 8; j++) { acc[i][j][0] = 0u; acc[i][j][1] = 0u; }

    auto issue = [&](int s, int kt) {
        const uint32_t stA = sb + s * STAGE_BYTES;
        const int k0 = kt * BKB;
#pragma unroll
        for (int i = 0; i < 8; i++) {
            int task = i * 256 + tid;
            if (task < 1024) {
                int row = task >> 3, ch = task & 7;
                uint32_t rel = (uint32_t)(row * ROWB + ch * 16);
                CPA16(stA + SWZ(rel), Ab + (size_t)row * HDIM + k0 + ch * 16);
            } else {
                int t2 = task - 1024;
                int row = t2 >> 3, ch = t2 & 7;
                uint32_t rel = (uint32_t)(row * ROWB + ch * 16);
                CPA16(stA + A_BYTES + SWZ(rel), Bb + (size_t)row * HDIM + k0 + ch * 16);
            }
        }
    };

    const uint32_t lr = (uint32_t)(lane & 15);
    const uint32_t lc16 = (uint32_t)(lane >> 4) * 16;

    // fragment loader for one kk sub-step
    auto load_frags = [&](uint32_t aB, uint32_t bB, int kk,
                          uint32_t af[2][4], uint32_t bfr[4][4]) {
        const uint32_t cb = (uint32_t)kk * 32 + lc16;
#pragma unroll
        for (int mi = 0; mi < 2; mi++) {
            uint32_t rel = (uint32_t)(wm * 32 + mi * 16 + lr) * ROWB + cb;
            ldmx4(af[mi], aB + SWZ(rel));
        }
#pragma unroll
        for (int nb = 0; nb < 4; nb++) {
            uint32_t rel = (uint32_t)(wn * 64 + nb * 16 + lr) * ROWB + cb;
            ldmx4(bfr[nb], bB + SWZ(rel));
        }
    };

    issue(0, 0); CP_COMMIT();
    issue(1, 1); CP_COMMIT();

    int st = 0;
    for (int kt = 0; kt < NK; kt++) {
        if (kt == NK - 1) { CP_WAIT0(); } else { CP_WAIT1(); }
        __syncthreads();
        if (kt + 2 < NK) {
            int ps = st + 2; if (ps >= NSTAGE) ps -= NSTAGE;
            issue(ps, kt + 2);
            CP_COMMIT();
        }
        const uint32_t aB = sb + st * STAGE_BYTES;
        const uint32_t bB = aB + A_BYTES;

        uint32_t af[2][2][4], bfr[2][4][4];
        load_frags(aB, bB, 0, af[0], bfr[0]);
#pragma unroll
        for (int kk = 0; kk < 4; kk++) {
            const int cur = kk & 1;
            if (kk < 3) load_frags(aB, bB, kk + 1, af[cur ^ 1], bfr[cur ^ 1]);
#pragma unroll
            for (int mi = 0; mi < 2; mi++)
#pragma unroll
                for (int nj = 0; nj < 8; nj++)
                    mma_fp8_h(acc[mi][nj], af[cur][mi],
                              bfr[cur][nj >> 1][nj & 1], bfr[cur][nj >> 1][2 + (nj & 1)]);
        }
        if (++st == NSTAGE) st = 0;
    }

    // ------- epilogue: f16->f32, scale, + bias, per-row LSE over 128 cols ----------
    const int qr = lane >> 2, qc = lane & 3;
    float bb[16];
#pragma unroll
    for (int nj = 0; nj < 8; nj++) {
        int col = ntile * BN + wn * 64 + nj * 8 + qc * 2;
        bb[2 * nj]     = __ldg(bias + col);
        bb[2 * nj + 1] = __ldg(bias + col + 1);
    }
    float v[2][8][4];
#pragma unroll
    for (int mi = 0; mi < 2; mi++)
#pragma unroll
        for (int nj = 0; nj < 8; nj++) {
#pragma unroll
            for (int h = 0; h < 2; h++) {
                __half2 hv = *reinterpret_cast<__half2*>(&acc[mi][nj][h]);
                float2 f = __half22float2(hv);
                v[mi][nj][2 * h]     = f.x * INVS + bb[2 * nj];
                v[mi][nj][2 * h + 1] = f.y * INVS + bb[2 * nj + 1];
            }
        }

    float* sMax = (float*)(smem + RED_OFF);          // [128][2]
    float* sSum = (float*)(smem + RED_OFF + 1024);   // [128][2]
#pragma unroll
    for (int mi = 0; mi < 2; mi++) {
#pragma unroll
        for (int h = 0; h < 2; h++) {
            float m = -3.0e38f;
#pragma unroll
            for (int nj = 0; nj < 8; nj++)
                m = fmaxf(m, fmaxf(v[mi][nj][2 * h], v[mi][nj][2 * h + 1]));
            m = fmaxf(m, __shfl_xor_sync(0xffffffffu, m, 1));
            m = fmaxf(m, __shfl_xor_sync(0xffffffffu, m, 2));
            float s = 0.f;
#pragma unroll
            for (int nj = 0; nj < 8; nj++) {
                s += __expf(v[mi][nj][2 * h] - m);
                s += __expf(v[mi][nj][2 * h + 1] - m);
            }
            s += __shfl_xor_sync(0xffffffffu, s, 1);
            s += __shfl_xor_sync(0xffffffffu, s, 2);
            if (qc == 0) {
                int r = wm * 32 + mi * 16 + h * 8 + qr;
                sMax[r * 2 + wn] = m;
                sSum[r * 2 + wn] = s;
            }
        }
    }
    __syncthreads();
    if (tid < BM) {
        float ma = sMax[tid * 2], mb = sMax[tid * 2 + 1];
        float mm = fmaxf(ma, mb);
        float ss = sSum[tid * 2] * __expf(ma - mm) + sSum[tid * 2 + 1] * __expf(mb - mm);
        g_plse[model][mtile * BM + tid][ntile] = mm + logf(ss);
    }
}

// ---------------- kernel 3: exact fp32 target logits ----------------
__global__ void tgt_kernel(const float* __restrict__ x0, const float* __restrict__ w0,
                           const float* __restrict__ b0, const float* __restrict__ x1,
                           const float* __restrict__ w1, const float* __restrict__ b1) {
    int gw = (int)((blockIdx.x * blockDim.x + threadIdx.x) >> 5);
    int lane = threadIdx.x & 31;
    if (gw >= 2 * BTOK) return;
    int model = gw >> 12, t = gw & (BTOK - 1);
    int tg = g_tidx[t];
    float r = 0.f;
    if (tg >= 0 && tg < VDIM) {
        const float4* x4 = (const float4*)((model ? x1 : x0) + (size_t)t * HDIM);
        const float4* w4 = (const float4*)((model ? w1 : w0) + (size_t)tg * HDIM);
        float s = 0.f;
        for (int k = lane; k < HDIM / 4; k += 32) {
            float4 a = x4[k], bbk = w4[k];
            s = fmaf(a.x, bbk.x, fmaf(a.y, bbk.y, fmaf(a.z, bbk.z, fmaf(a.w, bbk.w, s))));
        }
#pragma unroll
        for (int o = 16; o; o >>= 1) s += __shfl_xor_sync(0xffffffffu, s, o);
        r = s + (model ? b1 : b0)[tg];
    }
    if (lane == 0) g_tgt[model][t] = r;
}

// ---------------- kernel 4: merge partial LSEs ----------------
__global__ void lse_kernel() {
    int gw = (int)((blockIdx.x * blockDim.x + threadIdx.x) >> 5);
    int lane = threadIdx.x & 31;
    if (gw >= 2 * BTOK) return;
    int model = gw >> 12, t = gw & (BTOK - 1);
    float m = -3.0e38f;
    for (int i = lane; i < NTIL; i += 32) m = fmaxf(m, g_plse[model][t][i]);
#pragma unroll
    for (int o = 16; o; o >>= 1) m = fmaxf(m, __shfl_xor_sync(0xffffffffu, m, o));
    float s = 0.f;
    for (int i = lane; i < NTIL; i += 32) s += expf(g_plse[model][t][i] - m);
#pragma unroll
    for (int o = 16; o; o >>= 1) s += __shfl_xor_sync(0xffffffffu, s, o);
    if (lane == 0) {
        int tg = g_tidx[t];
        g_logp[model][t] = (tg == IGNORE_IDX) ? 0.f : (g_tgt[model][t] - (m + logf(s)));
    }
}

// ---------------- kernel 5: sequence sums + DPO loss ----------------
__global__ void loss_kernel(float* __restrict__ out) {
    __shared__ double seq[16];
    int tid = threadIdx.x;
    if (tid < 16) {
        int model = tid >> 3, s = tid & 7;
        double a = 0.0;
        for (int t = 0; t < SEQT; t++) a += (double)g_logp[model][s * SEQT + t];
        seq[tid] = a;
    }
    __syncthreads();
    if (tid == 0) {
        double L = 0.0;
        for (int p = 0; p < 4; p++) {
            double c = seq[p], r = seq[4 + p];
            double rc = seq[8 + p], rr = seq[12 + p];
            double d = 0.1 * ((c - rc) - (r - rr));
            double nl = (d > 0.0) ? log1p(exp(-d)) : (-d + log1p(exp(d)));
            L += nl;
        }
        out[0] = (float)(L / 4.0);
    }
}

// ---------------- launch ----------------
extern "C" void kernel_launch(void* const* d_in, const int* in_sizes, int n_in,
                              void* d_out, int out_size) {
    const float* x  = (const float*)d_in[0];
    const float* w  = (const float*)d_in[1];
    const float* b  = (const float*)d_in[2];
    const float* rx = (const float*)d_in[3];
    const float* rw = (const float*)d_in[4];
    const float* rb = (const float*)d_in[5];
    const void*  tg = d_in[6];

    norm_targets_kernel<<<1, 256>>>(tg);

    unsigned gx  = (unsigned)(((size_t)BTOK * HDIM / 4 + 511) / 512);
    unsigned gwv = (unsigned)(((size_t)VDIM * HDIM / 4 + 511) / 512);
    convert_x_kernel<<<dim3(gx, 2), 256>>>((const float4*)x, (const float4*)rx);
    convert_w_kernel<<<dim3(gwv, 2), 256>>>((const float4*)w, (const float4*)rw);

    cudaFuncSetAttribute(gemm_lse_kernel,
                         cudaFuncAttributeMaxDynamicSharedMemorySize, SMEM_GEMM);
    dim3 gg(BTOK / BM, VDIM / BN, 2);   // (32, 250, 2), mtile fastest
    gemm_lse_kernel<<<gg, 256, SMEM_GEMM>>>(b, rb);

    tgt_kernel<<<(2 * BTOK) / 8, 256>>>(x, w, b, rx, rw, rb);
    lse_kernel<<<(2 * BTOK) / 8, 256>>>();
    loss_kernel<<<1, 256>>>((float*)d_out);
}

// round 17
// speedup vs baseline: 1.0575x; 1.0181x over previous
#include <cuda_runtime.h>
#include <cuda_bf16.h>
#include <cuda_fp16.h>
#include <cstdint>
#include <cstddef>

// ---------------- problem constants ----------------
#define BTOK 4096
#define HDIM 4096
#define VDIM 32000
#define SEQT 512
#define IGNORE_IDX (-100)

// ---------------- FP8 GEMM tiling (champion geometry, split-barrier pipeline) -----
#define BM 128
#define BN 128
#define BKB 128                  // K bytes per chunk
#define NK (HDIM / BKB)          // 32 chunks
#define NSTAGE 3
#define ROWB 128
#define A_BYTES (BM * ROWB)      // 16384
#define STAGE_BYTES (A_BYTES + BN * ROWB)   // 32768
#define RED_OFF (NSTAGE * STAGE_BYTES)      // 98304
#define SMEM_GEMM (RED_OFF + 2048)
#define NTIL (VDIM / BN)         // 250
#define SCALE 64.0f
#define INVS (1.0f / 4096.0f)

#define SWZ(o) ((o) ^ (((o) >> 3) & 0x70))

// named barriers: FULL[s] = 1+s (stage data ready), EMPTY[s] = 4+s (stage reads done)
#define BARS(id) asm volatile("bar.sync %0, 512;"   :: "r"(id) : "memory")
#define BARA(id) asm volatile("bar.arrive %0, 512;" :: "r"(id) : "memory")
#define MEMBAR_CTA() asm volatile("membar.cta;" ::: "memory")

// ---------------- device scratch ----------------
__device__ __align__(256) uint8_t g_xq[2][(size_t)BTOK * HDIM];
__device__ __align__(256) uint8_t g_wq[2][(size_t)VDIM * HDIM];
__device__ float g_plse[2][BTOK][NTIL];
__device__ float g_tgt[2][BTOK];
__device__ float g_logp[2][BTOK];
__device__ int   g_tidx[BTOK];

// ---------------- helpers ----------------
__device__ __forceinline__ uint32_t smem_u32(const void* p) {
    return (uint32_t)__cvta_generic_to_shared(p);
}
__device__ __forceinline__ void ldmx4(uint32_t* r, uint32_t addr) {
    asm volatile("ldmatrix.sync.aligned.m8n8.x4.shared.b16 {%0,%1,%2,%3}, [%4];\n"
                 : "=r"(r[0]), "=r"(r[1]), "=r"(r[2]), "=r"(r[3]) : "r"(addr));
}
// fp8 x fp8 -> fp16 accumulators (best measured path on sm_103 legacy pipe)
__device__ __forceinline__ void mma_fp8_h(uint32_t* d, const uint32_t* a,
                                          uint32_t b0, uint32_t b1) {
    asm volatile("mma.sync.aligned.m16n8k32.row.col.f16.e4m3.e4m3.f16 "
                 "{%0,%1}, {%2,%3,%4,%5}, {%6,%7}, {%0,%1};\n"
                 : "+r"(d[0]), "+r"(d[1])
                 : "r"(a[0]), "r"(a[1]), "r"(a[2]), "r"(a[3]), "r"(b0), "r"(b1));
}
#define CPA16(dst, src) asm volatile("cp.async.cg.shared.global [%0], [%1], 16;" :: "r"(dst), "l"(src))
#define CP_COMMIT()     asm volatile("cp.async.commit_group;")
#define CP_WAIT1()      asm volatile("cp.async.wait_group 1;")
#define CP_WAIT0()      asm volatile("cp.async.wait_group 0;")

__device__ __forceinline__ uint32_t pack4_e4m3(float f0, float f1, float f2, float f3) {
    uint16_t lo, hi;
    asm("cvt.rn.satfinite.e4m3x2.f32 %0, %1, %2;" : "=h"(lo) : "f"(f1), "f"(f0));
    asm("cvt.rn.satfinite.e4m3x2.f32 %0, %1, %2;" : "=h"(hi) : "f"(f3), "f"(f2));
    return (uint32_t)lo | ((uint32_t)hi << 16);
}

// ---------------- kernel 0: normalize targets ----------------
__global__ void norm_targets_kernel(const void* traw) {
    __shared__ int notI64;
    const int* t32 = (const int*)traw;
    if (threadIdx.x == 0) notI64 = 0;
    __syncthreads();
    for (int i = threadIdx.x; i < BTOK / 2; i += blockDim.x) {
        int hi = t32[2 * i + 1];
        if (hi != 0 && hi != -1) notI64 = 1;
    }
    __syncthreads();
    if (notI64) {
        for (int i = threadIdx.x; i < BTOK; i += blockDim.x) g_tidx[i] = t32[i];
    } else {
        const long long* t64 = (const long long*)traw;
        for (int i = threadIdx.x; i < BTOK; i += blockDim.x) g_tidx[i] = (int)t64[i];
    }
}

// ---------------- kernel 1a: activations fp32 -> scaled e4m3 (2 granules/thread) --
__global__ void convert_x_kernel(const float4* __restrict__ x0, const float4* __restrict__ x1) {
    const size_t n4 = (size_t)BTOK * HDIM / 4;
    const int model = blockIdx.y;
    const float4* __restrict__ src = model ? x1 : x0;
    uint32_t* __restrict__ dst = reinterpret_cast<uint32_t*>(g_xq[model]);
    size_t i = (size_t)blockIdx.x * blockDim.x + threadIdx.x;
    const size_t stride = (size_t)gridDim.x * blockDim.x;
#pragma unroll
    for (int r = 0; r < 2; r++) {
        if (i < n4) {
            float4 v = src[i];
            dst[i] = pack4_e4m3(v.x * SCALE, v.y * SCALE, v.z * SCALE, v.w * SCALE);
        }
        i += stride;
    }
}
// ---------------- kernel 1b: weights (2 granules/thread, both models) ------------
__global__ void convert_w_kernel(const float4* __restrict__ w0, const float4* __restrict__ w1) {
    const size_t n4 = (size_t)VDIM * HDIM / 4;
    const int model = blockIdx.y;
    const float4* __restrict__ src = model ? w1 : w0;
    uint32_t* __restrict__ dst = reinterpret_cast<uint32_t*>(g_wq[model]);
    size_t i = (size_t)blockIdx.x * blockDim.x + threadIdx.x;
    const size_t stride = (size_t)gridDim.x * blockDim.x;
#pragma unroll
    for (int r = 0; r < 2; r++) {
        if (i < n4) {
            float4 v = src[i];
            dst[i] = pack4_e4m3(v.x * SCALE, v.y * SCALE, v.z * SCALE, v.w * SCALE);
        }
        i += stride;
    }
}

// ---------------- kernel 2: FP8 GEMM, fp16 accum, split-barrier pipeline ----------
// 8 warps, warp tile 32x64, 3-stage ring. Named-barrier arrive/sync pairs replace
// the blocking per-chunk __syncthreads: no warp blocks while holding unissued MMAs.
__global__ void __launch_bounds__(256, 2)
gemm_lse_kernel(const float* __restrict__ bias0, const float* __restrict__ bias1) {
    extern __shared__ char smem[];
    const uint32_t sb = smem_u32(smem);
    const int mtile = blockIdx.x, ntile = blockIdx.y, model = blockIdx.z;
    const uint8_t* __restrict__ Ab = g_xq[model] + (size_t)(mtile * BM) * HDIM;
    const uint8_t* __restrict__ Bb = g_wq[model] + (size_t)(ntile * BN) * HDIM;
    const float* __restrict__ bias = model ? bias1 : bias0;

    const int tid = threadIdx.x;
    const int lane = tid & 31, warp = tid >> 5;
    const int wm = warp & 3, wn = warp >> 2;   // 4x2 warps, warp tile 32x64

    uint32_t acc[2][8][2];                     // f16x2 accumulators
#pragma unroll
    for (int i = 0; i < 2; i++)
#pragma unroll
        for (int j = 0; j < 8; j++) { acc[i][j][0] = 0u; acc[i][j][1] = 0u; }

    auto issue = [&](int s, int kt) {
        const uint32_t stA = sb + s * STAGE_BYTES;
        const int k0 = kt * BKB;
#pragma unroll
        for (int i = 0; i < 8; i++) {
            int task = i * 256 + tid;
            if (task < 1024) {
                int row = task >> 3, ch = task & 7;
                uint32_t rel = (uint32_t)(row * ROWB + ch * 16);
                CPA16(stA + SWZ(rel), Ab + (size_t)row * HDIM + k0 + ch * 16);
            } else {
                int t2 = task - 1024;
                int row = t2 >> 3, ch = t2 & 7;
                uint32_t rel = (uint32_t)(row * ROWB + ch * 16);
                CPA16(stA + A_BYTES + SWZ(rel), Bb + (size_t)row * HDIM + k0 + ch * 16);
            }
        }
    };

    const uint32_t lr = (uint32_t)(lane & 15);
    const uint32_t lc16 = (uint32_t)(lane >> 4) * 16;

    auto load_frags = [&](uint32_t aB, uint32_t bB, int kk,
                          uint32_t af[2][4], uint32_t bfr[4][4]) {
        const uint32_t cb = (uint32_t)kk * 32 + lc16;
#pragma unroll
        for (int mi = 0; mi < 2; mi++) {
            uint32_t rel = (uint32_t)(wm * 32 + mi * 16 + lr) * ROWB + cb;
            ldmx4(af[mi], aB + SWZ(rel));
        }
#pragma unroll
        for (int nb = 0; nb < 4; nb++) {
            uint32_t rel = (uint32_t)(wn * 64 + nb * 16 + lr) * ROWB + cb;
            ldmx4(bfr[nb], bB + SWZ(rel));
        }
    };
    auto mma_group = [&](uint32_t af[2][4], uint32_t bfr[4][4]) {
#pragma unroll
        for (int mi = 0; mi < 2; mi++)
#pragma unroll
            for (int nj = 0; nj < 8; nj++)
                mma_fp8_h(acc[mi][nj], af[mi],
                          bfr[nj >> 1][nj & 1], bfr[nj >> 1][2 + (nj & 1)]);
    };

    // prologue: fill stages 0,1; publish FULL[0]; prime EMPTY[2]
    issue(0, 0); CP_COMMIT();
    issue(1, 1); CP_COMMIT();
    CP_WAIT1();
    MEMBAR_CTA();
    BARA(1 + 0);   // FULL[0]
    BARA(4 + 2);   // EMPTY[2] primed (never read yet)

    int st = 0;
    for (int kt = 0; kt < NK; kt++) {
        BARS(1 + st);                              // stage st data ready (all threads)
        const uint32_t aB = sb + st * STAGE_BYTES;
        const uint32_t bB = aB + A_BYTES;

        uint32_t af[2][2][4], bfr[2][4][4];
        load_frags(aB, bB, 0, af[0], bfr[0]);
        load_frags(aB, bB, 1, af[1], bfr[1]);
        mma_group(af[0], bfr[0]);                  // kk0
        load_frags(aB, bB, 2, af[0], bfr[0]);
        mma_group(af[1], bfr[1]);                  // kk1
        load_frags(aB, bB, 3, af[1], bfr[1]);
        BARA(4 + st);                              // all our reads of stage st issued
        mma_group(af[0], bfr[0]);                  // kk2
        mma_group(af[1], bfr[1]);                  // kk3

        const int nxt = (st + 1 == NSTAGE) ? 0 : st + 1;
        if (kt + 2 < NK) {
            int ps = st + 2; if (ps >= NSTAGE) ps -= NSTAGE;
            BARS(4 + ps);                          // stage ps free (readers arrived)
            issue(ps, kt + 2); CP_COMMIT();
            CP_WAIT1();                            // chunk kt+1's group now complete
            MEMBAR_CTA();
            BARA(1 + nxt);                         // publish FULL[(kt+1)%3]
        } else if (kt + 1 < NK) {
            CP_WAIT0();
            MEMBAR_CTA();
            BARA(1 + nxt);
        }
        st = nxt;
    }

    // ------- epilogue: f16->f32, scale, + bias, per-row LSE over 128 cols ----------
    const int qr = lane >> 2, qc = lane & 3;
    float bb[16];
#pragma unroll
    for (int nj = 0; nj < 8; nj++) {
        int col = ntile * BN + wn * 64 + nj * 8 + qc * 2;
        bb[2 * nj]     = __ldg(bias + col);
        bb[2 * nj + 1] = __ldg(bias + col + 1);
    }
    float v[2][8][4];
#pragma unroll
    for (int mi = 0; mi < 2; mi++)
#pragma unroll
        for (int nj = 0; nj < 8; nj++) {
#pragma unroll
            for (int h = 0; h < 2; h++) {
                __half2 hv = *reinterpret_cast<__half2*>(&acc[mi][nj][h]);
                float2 f = __half22float2(hv);
                v[mi][nj][2 * h]     = f.x * INVS + bb[2 * nj];
                v[mi][nj][2 * h + 1] = f.y * INVS + bb[2 * nj + 1];
            }
        }

    __syncthreads();                                // close mainloop before smem reuse
    float* sMax = (float*)(smem + RED_OFF);          // [128][2]
    float* sSum = (float*)(smem + RED_OFF + 1024);   // [128][2]
#pragma unroll
    for (int mi = 0; mi < 2; mi++) {
#pragma unroll
        for (int h = 0; h < 2; h++) {
            float m = -3.0e38f;
#pragma unroll
            for (int nj = 0; nj < 8; nj++)
                m = fmaxf(m, fmaxf(v[mi][nj][2 * h], v[mi][nj][2 * h + 1]));
            m = fmaxf(m, __shfl_xor_sync(0xffffffffu, m, 1));
            m = fmaxf(m, __shfl_xor_sync(0xffffffffu, m, 2));
            float s = 0.f;
#pragma unroll
            for (int nj = 0; nj < 8; nj++) {
                s += __expf(v[mi][nj][2 * h] - m);
                s += __expf(v[mi][nj][2 * h + 1] - m);
            }
            s += __shfl_xor_sync(0xffffffffu, s, 1);
            s += __shfl_xor_sync(0xffffffffu, s, 2);
            if (qc == 0) {
                int r = wm * 32 + mi * 16 + h * 8 + qr;
                sMax[r * 2 + wn] = m;
                sSum[r * 2 + wn] = s;
            }
        }
    }
    __syncthreads();
    if (tid < BM) {
        float ma = sMax[tid * 2], mb = sMax[tid * 2 + 1];
        float mm = fmaxf(ma, mb);
        float ss = sSum[tid * 2] * __expf(ma - mm) + sSum[tid * 2 + 1] * __expf(mb - mm);
        g_plse[model][mtile * BM + tid][ntile] = mm + logf(ss);
    }
}

// ---------------- kernel 3: exact fp32 target logits ----------------
__global__ void tgt_kernel(const float* __restrict__ x0, const float* __restrict__ w0,
                           const float* __restrict__ b0, const float* __restrict__ x1,
                           const float* __restrict__ w1, const float* __restrict__ b1) {
    int gw = (int)((blockIdx.x * blockDim.x + threadIdx.x) >> 5);
    int lane = threadIdx.x & 31;
    if (gw >= 2 * BTOK) return;
    int model = gw >> 12, t = gw & (BTOK - 1);
    int tg = g_tidx[t];
    float r = 0.f;
    if (tg >= 0 && tg < VDIM) {
        const float4* x4 = (const float4*)((model ? x1 : x0) + (size_t)t * HDIM);
        const float4* w4 = (const float4*)((model ? w1 : w0) + (size_t)tg * HDIM);
        float s = 0.f;
        for (int k = lane; k < HDIM / 4; k += 32) {
            float4 a = x4[k], bbk = w4[k];
            s = fmaf(a.x, bbk.x, fmaf(a.y, bbk.y, fmaf(a.z, bbk.z, fmaf(a.w, bbk.w, s))));
        }
#pragma unroll
        for (int o = 16; o; o >>= 1) s += __shfl_xor_sync(0xffffffffu, s, o);
        r = s + (model ? b1 : b0)[tg];
    }
    if (lane == 0) g_tgt[model][t] = r;
}

// ---------------- kernel 4: merge partial LSEs ----------------
__global__ void lse_kernel() {
    int gw = (int)((blockIdx.x * blockDim.x + threadIdx.x) >> 5);
    int lane = threadIdx.x & 31;
    if (gw >= 2 * BTOK) return;
    int model = gw >> 12, t = gw & (BTOK - 1);
    float m = -3.0e38f;
    for (int i = lane; i < NTIL; i += 32) m = fmaxf(m, g_plse[model][t][i]);
#pragma unroll
    for (int o = 16; o; o >>= 1) m = fmaxf(m, __shfl_xor_sync(0xffffffffu, m, o));
    float s = 0.f;
    for (int i = lane; i < NTIL; i += 32) s += expf(g_plse[model][t][i] - m);
#pragma unroll
    for (int o = 16; o; o >>= 1) s += __shfl_xor_sync(0xffffffffu, s, o);
    if (lane == 0) {
        int tg = g_tidx[t];
        g_logp[model][t] = (tg == IGNORE_IDX) ? 0.f : (g_tgt[model][t] - (m + logf(s)));
    }
}

// ---------------- kernel 5: sequence sums + DPO loss ----------------
__global__ void loss_kernel(float* __restrict__ out) {
    __shared__ double seq[16];
    int tid = threadIdx.x;
    if (tid < 16) {
        int model = tid >> 3, s = tid & 7;
        double a = 0.0;
        for (int t = 0; t < SEQT; t++) a += (double)g_logp[model][s * SEQT + t];
        seq[tid] = a;
    }
    __syncthreads();
    if (tid == 0) {
        double L = 0.0;
        for (int p = 0; p < 4; p++) {
            double c = seq[p], r = seq[4 + p];
            double rc = seq[8 + p], rr = seq[12 + p];
            double d = 0.1 * ((c - rc) - (r - rr));
            double nl = (d > 0.0) ? log1p(exp(-d)) : (-d + log1p(exp(d)));
            L += nl;
        }
        out[0] = (float)(L / 4.0);
    }
}

// ---------------- launch ----------------
extern "C" void kernel_launch(void* const* d_in, const int* in_sizes, int n_in,
                              void* d_out, int out_size) {
    const float* x  = (const float*)d_in[0];
    const float* w  = (const float*)d_in[1];
    const float* b  = (const float*)d_in[2];
    const float* rx = (const float*)d_in[3];
    const float* rw = (const float*)d_in[4];
    const float* rb = (const float*)d_in[5];
    const void*  tg = d_in[6];

    norm_targets_kernel<<<1, 256>>>(tg);

    unsigned gx  = (unsigned)(((size_t)BTOK * HDIM / 4 + 511) / 512);
    unsigned gwv = (unsigned)(((size_t)VDIM * HDIM / 4 + 511) / 512);
    convert_x_kernel<<<dim3(gx, 2), 256>>>((const float4*)x, (const float4*)rx);
    convert_w_kernel<<<dim3(gwv, 2), 256>>>((const float4*)w, (const float4*)rw);

    cudaFuncSetAttribute(gemm_lse_kernel,
                         cudaFuncAttributeMaxDynamicSharedMemorySize, SMEM_GEMM);
    dim3 gg(BTOK / BM, VDIM / BN, 2);   // (32, 250, 2), mtile fastest
    gemm_lse_kernel<<<gg, 256, SMEM_GEMM>>>(b, rb);

    tgt_kernel<<<(2 * BTOK) / 8, 256>>>(x, w, b, rx, rw, rb);
    lse_kernel<<<(2 * BTOK) / 8, 256>>>();
    loss_kernel<<<1, 256>>>((float*)d_out);
}